// round 3
// baseline (speedup 1.0000x reference)
#include <cuda_runtime.h>
#include <cuda_bf16.h>
#include <cstdint>

#define N_NODES 100000
#define F 128
#define TR 64            // rows per transform block
#define LDT 65           // padded leading dim for transposed input tile

// Scratch (allocation-free rule: __device__ globals)
__device__ float g_agg[N_NODES * F];
__device__ float g_deg[N_NODES];

// ---------------------------------------------------------------------------
// Kernel A: zero the accumulators
// ---------------------------------------------------------------------------
__global__ void zero_kernel() {
    int idx = blockIdx.x * blockDim.x + threadIdx.x;
    int stride = gridDim.x * blockDim.x;
    float4 z = make_float4(0.f, 0.f, 0.f, 0.f);
    float4* a4 = (float4*)g_agg;
    int total4 = (N_NODES * F) / 4;
    for (int i = idx; i < total4; i += stride) a4[i] = z;
    for (int i = idx; i < N_NODES; i += stride) g_deg[i] = 0.f;
}

// ---------------------------------------------------------------------------
// Kernel B: edge scatter. One warp per edge: gather x[src] (512B), vector
// reduction-add into g_agg[dst]. Lane 0 bumps the degree counter.
// edge_index is int32 (JAX x64 disabled downcasts int64 -> int32).
// ---------------------------------------------------------------------------
__global__ void scatter_kernel(const int* __restrict__ ei, int E,
                               const float* __restrict__ x) {
    int gtid = blockIdx.x * blockDim.x + threadIdx.x;
    int warp = gtid >> 5;
    int lane = gtid & 31;
    int nW = (gridDim.x * blockDim.x) >> 5;
    for (int e = warp; e < E; e += nW) {
        int s = ei[e];
        int d = ei[E + e];
        if ((unsigned)s >= (unsigned)N_NODES ||
            (unsigned)d >= (unsigned)N_NODES) continue;
        float4 v = ((const float4*)(x + (long long)s * F))[lane];
        float4* dp = ((float4*)(g_agg + (long long)d * F)) + lane;
        asm volatile("red.global.add.v4.f32 [%0], {%1,%2,%3,%4};"
                     :: "l"(dp), "f"(v.x), "f"(v.y), "f"(v.z), "f"(v.w)
                     : "memory");
        if (lane == 0) atomicAdd(&g_deg[d], 1.0f);
    }
}

// ---------------------------------------------------------------------------
// Kernel C: fused transform.
//   out[i] = (S[i]/max(deg,1)) @ W_l^T + 1{deg>0}*b_l + x[i] @ W_r^T
// One GEMM: in256 = [S*scale ; x], W256 = [W_l ; W_r] transposed in smem.
// 64 rows/block, 4x8 register tile per thread, 256 threads.
// ---------------------------------------------------------------------------
__global__ void __launch_bounds__(256, 1)
transform_kernel(const float* __restrict__ x,
                 const float* __restrict__ W_l,
                 const float* __restrict__ b_l,
                 const float* __restrict__ W_r,
                 float* __restrict__ out) {
    extern __shared__ float sm[];
    float* Wt  = sm;                 // [256][128]
    float* inT = sm + 256 * 128;     // [256][LDT]
    __shared__ float s_bias[128];
    __shared__ float s_scale[TR];
    __shared__ float s_dflag[TR];

    int tid = threadIdx.x;
    int row0 = blockIdx.x * TR;

    // Load transposed weights: Wt[k*128 + c] = W[c][k]
    for (int idx = tid; idx < 256 * 128; idx += 256) {
        int k = idx >> 7;
        int c = idx & 127;
        Wt[idx] = (k < 128) ? W_l[c * 128 + k] : W_r[c * 128 + (k - 128)];
    }
    if (tid < 128) s_bias[tid] = b_l[tid];
    if (tid < TR) {
        int r = row0 + tid;
        float d = (r < N_NODES) ? g_deg[r] : 0.f;
        s_scale[tid] = 1.f / fmaxf(d, 1.f);
        s_dflag[tid] = (d > 0.f) ? 1.f : 0.f;
    }
    __syncthreads();

    // Fill transposed input tile: inT[k][r]
    for (int idx = tid; idx < TR * 128; idx += 256) {
        int r = idx >> 7;
        int k = idx & 127;
        int row = row0 + r;
        float av = 0.f, xv = 0.f;
        if (row < N_NODES) {
            av = g_agg[(long long)row * 128 + k] * s_scale[r];
            xv = x[(long long)row * 128 + k];
        }
        inT[k * LDT + r] = av;
        inT[(k + 128) * LDT + r] = xv;
    }
    __syncthreads();

    // 4 rows x 8 cols per thread. 16 col-groups x 16 row-groups.
    int cg = tid & 15;
    int rg = tid >> 4;
    float acc[4][8];
#pragma unroll
    for (int i = 0; i < 4; i++)
#pragma unroll
        for (int j = 0; j < 8; j++) acc[i][j] = 0.f;

    const float* aB = inT + rg * 4;
    const float* bB = Wt + cg * 8;

#pragma unroll 4
    for (int k = 0; k < 256; k++) {
        float a0 = aB[k * LDT + 0];
        float a1 = aB[k * LDT + 1];
        float a2 = aB[k * LDT + 2];
        float a3 = aB[k * LDT + 3];
        float4 b0 = *(const float4*)(bB + k * 128);
        float4 b1 = *(const float4*)(bB + k * 128 + 4);
        acc[0][0] += a0 * b0.x; acc[0][1] += a0 * b0.y;
        acc[0][2] += a0 * b0.z; acc[0][3] += a0 * b0.w;
        acc[0][4] += a0 * b1.x; acc[0][5] += a0 * b1.y;
        acc[0][6] += a0 * b1.z; acc[0][7] += a0 * b1.w;
        acc[1][0] += a1 * b0.x; acc[1][1] += a1 * b0.y;
        acc[1][2] += a1 * b0.z; acc[1][3] += a1 * b0.w;
        acc[1][4] += a1 * b1.x; acc[1][5] += a1 * b1.y;
        acc[1][6] += a1 * b1.z; acc[1][7] += a1 * b1.w;
        acc[2][0] += a2 * b0.x; acc[2][1] += a2 * b0.y;
        acc[2][2] += a2 * b0.z; acc[2][3] += a2 * b0.w;
        acc[2][4] += a2 * b1.x; acc[2][5] += a2 * b1.y;
        acc[2][6] += a2 * b1.z; acc[2][7] += a2 * b1.w;
        acc[3][0] += a3 * b0.x; acc[3][1] += a3 * b0.y;
        acc[3][2] += a3 * b0.z; acc[3][3] += a3 * b0.w;
        acc[3][4] += a3 * b1.x; acc[3][5] += a3 * b1.y;
        acc[3][6] += a3 * b1.z; acc[3][7] += a3 * b1.w;
    }

#pragma unroll
    for (int i = 0; i < 4; i++) {
        int row = row0 + rg * 4 + i;
        if (row < N_NODES) {
            float df = s_dflag[rg * 4 + i];
            float4 o0, o1;
            o0.x = acc[i][0] + df * s_bias[cg * 8 + 0];
            o0.y = acc[i][1] + df * s_bias[cg * 8 + 1];
            o0.z = acc[i][2] + df * s_bias[cg * 8 + 2];
            o0.w = acc[i][3] + df * s_bias[cg * 8 + 3];
            o1.x = acc[i][4] + df * s_bias[cg * 8 + 4];
            o1.y = acc[i][5] + df * s_bias[cg * 8 + 5];
            o1.z = acc[i][6] + df * s_bias[cg * 8 + 6];
            o1.w = acc[i][7] + df * s_bias[cg * 8 + 7];
            *(float4*)(out + (long long)row * 128 + cg * 8) = o0;
            *(float4*)(out + (long long)row * 128 + cg * 8 + 4) = o1;
        }
    }
}

// ---------------------------------------------------------------------------
// Launch
// ---------------------------------------------------------------------------
extern "C" void kernel_launch(void* const* d_in, const int* in_sizes, int n_in,
                              void* d_out, int out_size) {
    const float* x   = (const float*)d_in[0];
    const int*   ei  = (const int*)d_in[1];      // int32 edge_index [2, E]
    const float* W_l = (const float*)d_in[2];
    const float* b_l = (const float*)d_in[3];
    const float* W_r = (const float*)d_in[4];
    float*       out = (float*)d_out;
    int E = in_sizes[1] / 2;

    const int SMEM_BYTES = (256 * 128 + 256 * LDT) * (int)sizeof(float);
    cudaFuncSetAttribute(transform_kernel,
                         cudaFuncAttributeMaxDynamicSharedMemorySize,
                         SMEM_BYTES);

    zero_kernel<<<512, 256>>>();
    scatter_kernel<<<4096, 256>>>(ei, E, x);
    transform_kernel<<<(N_NODES + TR - 1) / TR, 256, SMEM_BYTES>>>(
        x, W_l, b_l, W_r, out);
}

// round 4
// speedup vs baseline: 1.1511x; 1.1511x over previous
#include <cuda_runtime.h>
#include <cuda_bf16.h>
#include <cstdint>

#define N_NODES 100000
#define F 128
#define MAXE 1600000
#define TR 64            // rows per transform block
#define LDT 65           // padded leading dim for transposed input tile
#define SCAN_BS 1024
#define SCAN_NB ((N_NODES + SCAN_BS - 1) / SCAN_BS)   // 98

// Scratch (allocation-free rule: __device__ globals)
__device__ float g_agg[N_NODES * F];   // scaled mean of neighbor features
__device__ int   g_cnt[N_NODES];       // degree (histogram)
__device__ int   g_cur[N_NODES];       // fill cursors
__device__ int   g_off[N_NODES];       // CSR offsets
__device__ int   g_bsum[SCAN_NB + 1];  // scan block sums
__device__ int   g_csr[MAXE];          // CSR column (src) indices

// ---------------------------------------------------------------------------
// A: zero the int arrays (g_agg is fully overwritten by aggregate, no zeroing)
// ---------------------------------------------------------------------------
__global__ void zero_kernel() {
    int idx = blockIdx.x * blockDim.x + threadIdx.x;
    int stride = gridDim.x * blockDim.x;
    for (int i = idx; i < N_NODES; i += stride) {
        g_cnt[i] = 0;
        g_cur[i] = 0;
    }
}

// ---------------------------------------------------------------------------
// B: degree histogram over dst indices (edge_index is int32)
// ---------------------------------------------------------------------------
__global__ void hist_kernel(const int* __restrict__ ei, int E) {
    int idx = blockIdx.x * blockDim.x + threadIdx.x;
    int stride = gridDim.x * blockDim.x;
    for (int e = idx; e < E; e += stride) {
        int d = ei[E + e];
        if ((unsigned)d < (unsigned)N_NODES) atomicAdd(&g_cnt[d], 1);
    }
}

// ---------------------------------------------------------------------------
// C1/C2/C3: exclusive scan of g_cnt -> g_off  (3-pass block scan)
// ---------------------------------------------------------------------------
__global__ void scan1_kernel() {
    __shared__ int s[SCAN_BS];
    int tid = threadIdx.x;
    int i = blockIdx.x * SCAN_BS + tid;
    int v = (i < N_NODES) ? g_cnt[i] : 0;
    s[tid] = v;
    __syncthreads();
#pragma unroll
    for (int d = 1; d < SCAN_BS; d <<= 1) {
        int t = (tid >= d) ? s[tid - d] : 0;
        __syncthreads();
        s[tid] += t;
        __syncthreads();
    }
    if (i < N_NODES) g_off[i] = s[tid] - v;   // exclusive
    if (tid == SCAN_BS - 1) g_bsum[blockIdx.x] = s[tid];
}

__global__ void scan2_kernel() {
    if (threadIdx.x == 0) {
        int run = 0;
        for (int b = 0; b < SCAN_NB; b++) {
            int t = g_bsum[b];
            g_bsum[b] = run;
            run += t;
        }
    }
}

__global__ void scan3_kernel() {
    int i = blockIdx.x * SCAN_BS + threadIdx.x;
    if (i < N_NODES) g_off[i] += g_bsum[blockIdx.x];
}

// ---------------------------------------------------------------------------
// D: CSR fill — csr[off[d] + cursor[d]++] = s
// ---------------------------------------------------------------------------
__global__ void fill_kernel(const int* __restrict__ ei, int E) {
    int idx = blockIdx.x * blockDim.x + threadIdx.x;
    int stride = gridDim.x * blockDim.x;
    for (int e = idx; e < E; e += stride) {
        int s = ei[e];
        int d = ei[E + e];
        if ((unsigned)s >= (unsigned)N_NODES ||
            (unsigned)d >= (unsigned)N_NODES) continue;
        int p = atomicAdd(&g_cur[d], 1);
        g_csr[g_off[d] + p] = s;
    }
}

// ---------------------------------------------------------------------------
// E: aggregate — one warp per dst node, gather + mean, single write, no atomics
// ---------------------------------------------------------------------------
__global__ void aggregate_kernel(const float* __restrict__ x) {
    int gtid = blockIdx.x * blockDim.x + threadIdx.x;
    int w = gtid >> 5;
    int lane = gtid & 31;
    if (w >= N_NODES) return;
    int off = g_off[w];
    int deg = g_cnt[w];
    int end = off + deg;

    float4 acc = make_float4(0.f, 0.f, 0.f, 0.f);
    int i = off;
    // 4-deep ILP over edges
    for (; i + 4 <= end; i += 4) {
        int s0 = g_csr[i + 0];
        int s1 = g_csr[i + 1];
        int s2 = g_csr[i + 2];
        int s3 = g_csr[i + 3];
        float4 v0 = ((const float4*)(x + (long long)s0 * F))[lane];
        float4 v1 = ((const float4*)(x + (long long)s1 * F))[lane];
        float4 v2 = ((const float4*)(x + (long long)s2 * F))[lane];
        float4 v3 = ((const float4*)(x + (long long)s3 * F))[lane];
        acc.x += (v0.x + v1.x) + (v2.x + v3.x);
        acc.y += (v0.y + v1.y) + (v2.y + v3.y);
        acc.z += (v0.z + v1.z) + (v2.z + v3.z);
        acc.w += (v0.w + v1.w) + (v2.w + v3.w);
    }
    for (; i < end; i++) {
        int s = g_csr[i];
        float4 v = ((const float4*)(x + (long long)s * F))[lane];
        acc.x += v.x; acc.y += v.y; acc.z += v.z; acc.w += v.w;
    }
    float sc = 1.f / fmaxf((float)deg, 1.f);
    acc.x *= sc; acc.y *= sc; acc.z *= sc; acc.w *= sc;
    ((float4*)(g_agg + (long long)w * F))[lane] = acc;
}

// ---------------------------------------------------------------------------
// F: fused transform.
//   out[i] = agg[i] @ W_l^T + 1{deg>0}*b_l + x[i] @ W_r^T
// One GEMM: in256 = [agg ; x], W256 = [W_l ; W_r] transposed in smem.
// 64 rows/block, 4x8 register tile per thread, 256 threads.
// ---------------------------------------------------------------------------
__global__ void __launch_bounds__(256, 1)
transform_kernel(const float* __restrict__ x,
                 const float* __restrict__ W_l,
                 const float* __restrict__ b_l,
                 const float* __restrict__ W_r,
                 float* __restrict__ out) {
    extern __shared__ float sm[];
    float* Wt  = sm;                 // [256][128]
    float* inT = sm + 256 * 128;     // [256][LDT]
    __shared__ float s_bias[128];
    __shared__ float s_dflag[TR];

    int tid = threadIdx.x;
    int row0 = blockIdx.x * TR;

    // Load transposed weights: Wt[k*128 + c] = W[c][k]
    for (int idx = tid; idx < 256 * 128; idx += 256) {
        int k = idx >> 7;
        int c = idx & 127;
        Wt[idx] = (k < 128) ? W_l[c * 128 + k] : W_r[c * 128 + (k - 128)];
    }
    if (tid < 128) s_bias[tid] = b_l[tid];
    if (tid < TR) {
        int r = row0 + tid;
        int d = (r < N_NODES) ? g_cnt[r] : 0;
        s_dflag[tid] = (d > 0) ? 1.f : 0.f;
    }
    __syncthreads();

    // Fill transposed input tile: inT[k][r]
    for (int idx = tid; idx < TR * 128; idx += 256) {
        int r = idx >> 7;
        int k = idx & 127;
        int row = row0 + r;
        float av = 0.f, xv = 0.f;
        if (row < N_NODES) {
            av = g_agg[(long long)row * 128 + k];   // already scaled
            xv = x[(long long)row * 128 + k];
        }
        inT[k * LDT + r] = av;
        inT[(k + 128) * LDT + r] = xv;
    }
    __syncthreads();

    // 4 rows x 8 cols per thread. 16 col-groups x 16 row-groups.
    int cg = tid & 15;
    int rg = tid >> 4;
    float acc[4][8];
#pragma unroll
    for (int i = 0; i < 4; i++)
#pragma unroll
        for (int j = 0; j < 8; j++) acc[i][j] = 0.f;

    const float* aB = inT + rg * 4;
    const float* bB = Wt + cg * 8;

#pragma unroll 4
    for (int k = 0; k < 256; k++) {
        float a0 = aB[k * LDT + 0];
        float a1 = aB[k * LDT + 1];
        float a2 = aB[k * LDT + 2];
        float a3 = aB[k * LDT + 3];
        float4 b0 = *(const float4*)(bB + k * 128);
        float4 b1 = *(const float4*)(bB + k * 128 + 4);
        acc[0][0] += a0 * b0.x; acc[0][1] += a0 * b0.y;
        acc[0][2] += a0 * b0.z; acc[0][3] += a0 * b0.w;
        acc[0][4] += a0 * b1.x; acc[0][5] += a0 * b1.y;
        acc[0][6] += a0 * b1.z; acc[0][7] += a0 * b1.w;
        acc[1][0] += a1 * b0.x; acc[1][1] += a1 * b0.y;
        acc[1][2] += a1 * b0.z; acc[1][3] += a1 * b0.w;
        acc[1][4] += a1 * b1.x; acc[1][5] += a1 * b1.y;
        acc[1][6] += a1 * b1.z; acc[1][7] += a1 * b1.w;
        acc[2][0] += a2 * b0.x; acc[2][1] += a2 * b0.y;
        acc[2][2] += a2 * b0.z; acc[2][3] += a2 * b0.w;
        acc[2][4] += a2 * b1.x; acc[2][5] += a2 * b1.y;
        acc[2][6] += a2 * b1.z; acc[2][7] += a2 * b1.w;
        acc[3][0] += a3 * b0.x; acc[3][1] += a3 * b0.y;
        acc[3][2] += a3 * b0.z; acc[3][3] += a3 * b0.w;
        acc[3][4] += a3 * b1.x; acc[3][5] += a3 * b1.y;
        acc[3][6] += a3 * b1.z; acc[3][7] += a3 * b1.w;
    }

#pragma unroll
    for (int i = 0; i < 4; i++) {
        int row = row0 + rg * 4 + i;
        if (row < N_NODES) {
            float df = s_dflag[rg * 4 + i];
            float4 o0, o1;
            o0.x = acc[i][0] + df * s_bias[cg * 8 + 0];
            o0.y = acc[i][1] + df * s_bias[cg * 8 + 1];
            o0.z = acc[i][2] + df * s_bias[cg * 8 + 2];
            o0.w = acc[i][3] + df * s_bias[cg * 8 + 3];
            o1.x = acc[i][4] + df * s_bias[cg * 8 + 4];
            o1.y = acc[i][5] + df * s_bias[cg * 8 + 5];
            o1.z = acc[i][6] + df * s_bias[cg * 8 + 6];
            o1.w = acc[i][7] + df * s_bias[cg * 8 + 7];
            *(float4*)(out + (long long)row * 128 + cg * 8) = o0;
            *(float4*)(out + (long long)row * 128 + cg * 8 + 4) = o1;
        }
    }
}

// ---------------------------------------------------------------------------
// Launch
// ---------------------------------------------------------------------------
extern "C" void kernel_launch(void* const* d_in, const int* in_sizes, int n_in,
                              void* d_out, int out_size) {
    const float* x   = (const float*)d_in[0];
    const int*   ei  = (const int*)d_in[1];      // int32 edge_index [2, E]
    const float* W_l = (const float*)d_in[2];
    const float* b_l = (const float*)d_in[3];
    const float* W_r = (const float*)d_in[4];
    float*       out = (float*)d_out;
    int E = in_sizes[1] / 2;
    if (E > MAXE) E = MAXE;

    const int SMEM_BYTES = (256 * 128 + 256 * LDT) * (int)sizeof(float);
    cudaFuncSetAttribute(transform_kernel,
                         cudaFuncAttributeMaxDynamicSharedMemorySize,
                         SMEM_BYTES);

    zero_kernel<<<256, 256>>>();
    hist_kernel<<<2048, 256>>>(ei, E);
    scan1_kernel<<<SCAN_NB, SCAN_BS>>>();
    scan2_kernel<<<1, 32>>>();
    scan3_kernel<<<SCAN_NB, SCAN_BS>>>();
    fill_kernel<<<2048, 256>>>(ei, E);
    aggregate_kernel<<<(N_NODES * 32 + 255) / 256, 256>>>(x);
    transform_kernel<<<(N_NODES + TR - 1) / TR, 256, SMEM_BYTES>>>(
        x, W_l, b_l, W_r, out);
}